// round 10
// baseline (speedup 1.0000x reference)
#include <cuda_runtime.h>
#include <cuda_fp16.h>
#include <cstdint>

#define RS   88                 // halves per smem row (176 B)
#define MB   16                 // rows per block
#define ASZH (MB * RS)          // halves per A buffer
#define SMEM_BYTES ((2 * ASZH + 256 * RS) * 2)   // 50688

// ---------------- scratch ----------------
__device__ float g_feat[2 * 32 * 2 * 64 * 55];   // [sub][b][7040]
__device__ float g_y1[64 * 3400];
__device__ float g_y2[64 * 1000];
__device__ float g_y3[64 * 512];
__device__ float g_part[16 * 64 * 3400];

__device__ __forceinline__ float tanh_f(float x) {
    float r; asm("tanh.approx.f32 %0, %1;" : "=f"(r) : "f"(x)); return r;
}
// pre-activation already scaled by 0.5 (folded into weights)
__device__ __forceinline__ float sigm_pre(float xhalf) {
    return fmaf(0.5f, tanh_f(xhalf), 0.5f);
}

__device__ __forceinline__ uint32_t smem_u32(const void* p) {
    uint32_t a;
    asm("{ .reg .u64 t; cvta.to.shared.u64 t, %1; cvt.u32.u64 %0, t; }" : "=r"(a) : "l"(p));
    return a;
}

#define MMA16816(d, a0, a1, a2, a3, b0, b1) \
    asm volatile("mma.sync.aligned.m16n8k16.row.col.f32.f16.f16.f32 " \
        "{%0,%1,%2,%3}, {%4,%5,%6,%7}, {%8,%9}, {%0,%1,%2,%3};" \
        : "+f"((d)[0]), "+f"((d)[1]), "+f"((d)[2]), "+f"((d)[3]) \
        : "r"(a0), "r"(a1), "r"(a2), "r"(a3), "r"(b0), "r"(b1))

// ---------------- tensor-core LSTM (HMMA, 3 blocks/SM) ----------------
// grid = 440: blk/220 = cell, rb = (blk%220)*16 (exact, no padding).
// Warp w owns B cols [32w,32w+32): col n -> gate (n>>3)&3, channel 8w + (n&7).
// Lane owns rows {lane>>2, +8}, channels {8w+(lane&3)*2, +1}; full gate quad in-lane.
__global__ __launch_bounds__(256, 3)
void lstm_mma(const float* __restrict__ x1, const float* __restrict__ x2,
              const float* __restrict__ wx1, const float* __restrict__ wh1,
              const float* __restrict__ bx1, const float* __restrict__ bh1,
              const float* __restrict__ wx2, const float* __restrict__ wh2,
              const float* __restrict__ bx2, const float* __restrict__ bh2,
              float* __restrict__ feat)
{
    extern __shared__ __align__(16) __half smem[];
    __half* A0 = smem;
    __half* A1 = smem + ASZH;
    __half* Bw = smem + 2 * ASZH;

    int tid = threadIdx.x, wid = tid >> 5, lane = tid & 31;
    int blk = blockIdx.x;
    int cell = blk / 220;
    int rb   = (blk % 220) * MB;             // row base within cell-space (always full)

    const float* wh = cell ? wh2 : wh1;
    const float* wx = cell ? wx2 : wx1;
    const float* bx = cell ? bx2 : bx1;
    const float* bh = cell ? bh2 : bh1;

    // ---- build B (fp16, 0.5-prescaled for sigmoid gates i,f,o) ----
    {
        int n  = tid;
        int w  = n >> 5, g = (n >> 3) & 3, cl = n & 7;
        int gc = g * 64 + 8 * w + cl;        // source gate column
        float s = (g == 3) ? 1.0f : 0.5f;
        __half* bp = Bw + n * RS;
#pragma unroll 8
        for (int k = 0; k < 64; k++) bp[k] = __float2half(wh[k * 256 + gc] * s);
        bp[64] = __float2half(wx[gc] * s);
        bp[65] = __float2half(wx[256 + gc] * s);
        bp[66] = __float2half((bx[gc] + bh[gc]) * s);
#pragma unroll
        for (int k = 67; k < RS; k++) bp[k] = __float2half(0.f);
    }
    // ---- zero A buffers ----
    for (int i = tid; i < (2 * ASZH * 2) / 16; i += 256)
        ((uint4*)smem)[i] = make_uint4(0, 0, 0, 0);
    __syncthreads();

    // per-row x pointer (threads 0..15 own row tid)
    const float* xrp = nullptr;
    if (tid < MB) {
        int ric = rb + tid;
        int sub = ric / 1760, rem = ric % 1760, b = rem / 55, p = rem % 55;
        xrp = (sub ? x2 : x1) + (size_t)b * 256 * 110 + p;
        int t0 = cell ? 255 : 0;
        A0[tid * RS + 64] = __float2half(xrp[(size_t)t0 * 110]);
        A0[tid * RS + 65] = __float2half(xrp[(size_t)t0 * 110 + 55]);
        A0[tid * RS + 66] = __float2half(1.f);
        A1[tid * RS + 66] = __float2half(1.f);
    }
    __syncthreads();

    // B fragment base addresses (reloaded each step; keeps regs low for 3 blocks/SM)
    uint32_t baddr[4];
    {
        int li = lane & 15;
#pragma unroll
        for (int nt = 0; nt < 4; nt++)
            baddr[nt] = smem_u32(Bw + (wid * 32 + nt * 8 + (li & 7)) * RS
                                    + ((li >> 3) & 1) * 8);
    }

    uint32_t laneoff = (uint32_t)(((lane & 7) + 8 * ((lane >> 3) & 1)) * RS * 2
                                  + (lane >> 4) * 16);

    float cst[4] = {0.f, 0.f, 0.f, 0.f};     // rows {r0,r0+8} x chans {ch,ch+1}

    int r0 = lane >> 2;
    int ch = wid * 8 + (lane & 3) * 2;

    float xn0 = 0.f, xn1 = 0.f;

    for (int t = 0; t < 256; t++) {
        __half* Ac = (t & 1) ? A1 : A0;
        __half* An = (t & 1) ? A0 : A1;
        uint32_t abase = smem_u32(Ac) + laneoff;

        if (tid < MB && t < 255) {
            int tx = cell ? 254 - t : t + 1;
            xn0 = xrp[(size_t)tx * 110];
            xn1 = xrp[(size_t)tx * 110 + 55];
        }

        float acc[4][4];
#pragma unroll
        for (int nt = 0; nt < 4; nt++)
#pragma unroll
            for (int j = 0; j < 4; j++) acc[nt][j] = 0.f;

#pragma unroll
        for (int kt = 0; kt < 5; kt++) {
            uint32_t a0, a1, a2, a3;
            asm volatile("ldmatrix.sync.aligned.m8n8.x4.shared.b16 {%0,%1,%2,%3}, [%4];"
                         : "=r"(a0), "=r"(a1), "=r"(a2), "=r"(a3)
                         : "r"(abase + (uint32_t)(kt * 32)));
#pragma unroll
            for (int nt = 0; nt < 4; nt++) {
                uint32_t b0, b1;
                asm volatile("ldmatrix.sync.aligned.m8n8.x2.shared.b16 {%0,%1}, [%2];"
                             : "=r"(b0), "=r"(b1)
                             : "r"(baddr[nt] + (uint32_t)(kt * 32)));
                MMA16816(acc[nt], a0, a1, a2, a3, b0, b1);
            }
        }

        // epilogue: nt = gate (0:i 1:f 2:o 3:g); j: row-pair (j>>1), chan (j&1)
        float h01[2], h23[2];
#pragma unroll
        for (int j = 0; j < 4; j++) {
            float iv = sigm_pre(acc[0][j]);
            float fv = sigm_pre(acc[1][j]);
            float ov = sigm_pre(acc[2][j]);
            float gv = tanh_f(acc[3][j]);
            float cn = fmaf(fv, cst[j], iv * gv);
            cst[j] = cn;
            float h = ov * tanh_f(cn);
            if (j < 2) h01[j] = h; else h23[j - 2] = h;
        }
        *(__half2*)(An + r0 * RS + ch)       = __floats2half2_rn(h01[0], h01[1]);
        *(__half2*)(An + (r0 + 8) * RS + ch) = __floats2half2_rn(h23[0], h23[1]);

        if (t == 255) {
#pragma unroll
            for (int j = 0; j < 4; j++) {
                float h = (j < 2) ? h01[j] : h23[j - 2];
                int row = r0 + ((j >> 1) ? 8 : 0);
                int chh = ch + (j & 1);
                int ric = rb + row;
                int sub = ric / 1760, rem = ric % 1760, bb = rem / 55, pp = rem % 55;
                feat[(size_t)(sub * 32 + bb) * 7040 + cell * 3520 + chh * 55 + pp] = h;
            }
        }

        if (tid < MB && t < 255)
            *(__half2*)(An + tid * RS + 64) = __floats2half2_rn(xn0, xn1);

        __syncthreads();
    }
}

// ---------------- FC: K-split GEMM partials + reduce ----------------
__global__ __launch_bounds__(256)
void gemm_part(const float* __restrict__ X, const float* __restrict__ W,
               float* __restrict__ Ppart, int N, int K, int KS)
{
    int n0 = blockIdx.x * 64;
    int ks = blockIdx.y;
    int k0s = (int)(((long)K * ks) / KS);
    int k1s = (int)(((long)K * (ks + 1)) / KS);

    __shared__ float Asm[64][17];
    __shared__ float Bsm[16][65];

    int tid = threadIdx.x;
    int nl  = tid & 63;
    int mg  = tid >> 6;

    bool vec_ok = ((N & 3) == 0);   // float4 path only when W rows stay 16B-aligned

    float acc[16];
#pragma unroll
    for (int i = 0; i < 16; i++) acc[i] = 0.f;

    for (int k0 = k0s; k0 < k1s; k0 += 16) {
#pragma unroll
        for (int i = 0; i < 4; i++) {
            int rr = (tid >> 4) + i * 16;
            int cc = tid & 15;
            int k = k0 + cc;
            Asm[rr][cc] = (k < k1s) ? X[(size_t)rr * K + k] : 0.f;
        }
        {
            int rr = tid >> 4;            // 0..15
            int c4 = (tid & 15) * 4;      // 0..60
            int k  = k0 + rr;
            int nn = n0 + c4;
            if (vec_ok && k < k1s && nn + 3 < N) {
                float4 v = *(const float4*)&W[(size_t)k * N + nn];
                Bsm[rr][c4]     = v.x;
                Bsm[rr][c4 + 1] = v.y;
                Bsm[rr][c4 + 2] = v.z;
                Bsm[rr][c4 + 3] = v.w;
            } else {
#pragma unroll
                for (int e = 0; e < 4; e++)
                    Bsm[rr][c4 + e] = (k < k1s && nn + e < N)
                                      ? W[(size_t)k * N + nn + e] : 0.f;
            }
        }
        __syncthreads();
#pragma unroll
        for (int kk = 0; kk < 16; kk++) {
            float bv = Bsm[kk][nl];
#pragma unroll
            for (int i = 0; i < 16; i++)
                acc[i] += Asm[mg * 16 + i][kk] * bv;
        }
        __syncthreads();
    }

    int nn = n0 + nl;
    if (nn < N) {
        float* outp = Ppart + (size_t)ks * 64 * N;
#pragma unroll
        for (int i = 0; i < 16; i++)
            outp[(size_t)(mg * 16 + i) * N + nn] = acc[i];
    }
}

__global__ void reduce_bias(const float* __restrict__ Ppart, const float* __restrict__ bias,
                            float* __restrict__ Y, int N, int KS)
{
    int idx = blockIdx.x * 256 + threadIdx.x;
    if (idx >= 64 * N) return;
    int nn = idx % N;
    float s = bias[nn];
    for (int ks = 0; ks < KS; ks++) s += Ppart[(size_t)ks * 64 * N + idx];
    Y[idx] = s;
}

// ---------------- launch ----------------
extern "C" void kernel_launch(void* const* d_in, const int* in_sizes, int n_in,
                              void* d_out, int out_size)
{
    const float* x1  = (const float*)d_in[0];
    const float* x2  = (const float*)d_in[1];
    const float* wx1 = (const float*)d_in[2];
    const float* wh1 = (const float*)d_in[3];
    const float* bx1 = (const float*)d_in[4];
    const float* bh1 = (const float*)d_in[5];
    const float* wx2 = (const float*)d_in[6];
    const float* wh2 = (const float*)d_in[7];
    const float* bx2 = (const float*)d_in[8];
    const float* bh2 = (const float*)d_in[9];
    const float* fw2 = (const float*)d_in[10];
    const float* fb2 = (const float*)d_in[11];
    const float* fw3 = (const float*)d_in[12];
    const float* fb3 = (const float*)d_in[13];
    const float* fw4 = (const float*)d_in[14];
    const float* fb4 = (const float*)d_in[15];
    const float* fw5 = (const float*)d_in[16];
    const float* fb5 = (const float*)d_in[17];

    float *feat, *y1, *y2, *y3, *part;
    cudaGetSymbolAddress((void**)&feat, g_feat);
    cudaGetSymbolAddress((void**)&y1,   g_y1);
    cudaGetSymbolAddress((void**)&y2,   g_y2);
    cudaGetSymbolAddress((void**)&y3,   g_y3);
    cudaGetSymbolAddress((void**)&part, g_part);

    cudaFuncSetAttribute(lstm_mma, cudaFuncAttributeMaxDynamicSharedMemorySize, SMEM_BYTES);

    lstm_mma<<<440, 256, SMEM_BYTES>>>(x1, x2, wx1, wh1, bx1, bh1,
                                       wx2, wh2, bx2, bh2, feat);

    // FC1: 7040 -> 3400
    gemm_part<<<dim3(54, 16), 256>>>(feat, fw2, part, 3400, 7040, 16);
    reduce_bias<<<(64 * 3400 + 255) / 256, 256>>>(part, fb2, y1, 3400, 16);
    // FC2: 3400 -> 1000
    gemm_part<<<dim3(16, 8), 256>>>(y1, fw3, part, 1000, 3400, 8);
    reduce_bias<<<(64 * 1000 + 255) / 256, 256>>>(part, fb3, y2, 1000, 8);
    // FC3: 1000 -> 500
    gemm_part<<<dim3(8, 4), 256>>>(y2, fw4, part, 500, 1000, 4);
    reduce_bias<<<(64 * 500 + 255) / 256, 256>>>(part, fb4, y3, 500, 4);
    // FC4: 500 -> 50 -> d_out
    gemm_part<<<dim3(1, 2), 256>>>(y3, fw5, part, 50, 500, 2);
    reduce_bias<<<(64 * 50 + 255) / 256, 256>>>(part, fb5, (float*)d_out, 50, 2);
}